// round 6
// baseline (speedup 1.0000x reference)
#include <cuda_runtime.h>
#include <cstdint>

// Problem dims
#define TT 2048
#define BB 64
#define DD 128
#define HH 256
#define CC 5

// 134 MB scratch for x_proj (allowed: __device__ global, no runtime alloc)
__device__ float g_xproj[TT * BB * HH];

// ---------- helpers ----------
__device__ __forceinline__ float2 up2(unsigned long long v) {
    float2 r;
    asm("mov.b64 {%0,%1}, %2;" : "=f"(r.x), "=f"(r.y) : "l"(v));
    return r;
}
#define FMA2(d, a, b) asm("fma.rn.f32x2 %0, %1, %2, %0;" : "+l"(d) : "l"(a), "l"(b))

__device__ __forceinline__ uint32_t smem_u32(const void* p) {
    uint32_t a;
    asm("{ .reg .u64 t; cvta.to.shared.u64 t, %1; cvt.u32.u64 %0, t; }" : "=r"(a) : "l"(p));
    return a;
}

// fast tanh: 1 - 2/(e^{2x}+1), err ~5e-7, clamped
__device__ __forceinline__ float tanh_fast(float x) {
    float xc = fminf(fmaxf(x, -15.0f), 15.0f);
    float e  = __expf(2.0f * xc);
    return fmaf(-2.0f, __frcp_rn(e + 1.0f), 1.0f);
}

#define MBAR_WAIT(addr, parity)                                              \
    asm volatile(                                                            \
        "{\n\t.reg .pred P;\n"                                               \
        "W%=:\n\t"                                                           \
        "mbarrier.try_wait.parity.acquire.cta.shared::cta.b64 P, [%0], %1, 0x989680;\n\t" \
        "@!P bra W%=;\n\t}"                                                  \
        :: "r"(addr), "r"(parity) : "memory")

// =====================================================================
// Kernel 1: x_proj[t,b,j] = sum_k inputs[t,b,k] * W_ih[j,k] + b_ih[j] + b_hh[j]
// (unchanged from R5 — known good)
// =====================================================================
#define WPAD 130

__global__ __launch_bounds__(256) void xproj_kernel(
    const float* __restrict__ x, const float* __restrict__ Wih,
    const float* __restrict__ bih, const float* __restrict__ bhh)
{
    extern __shared__ float sm[];
    float* Wsm = sm;                    // [256][WPAD]
    float* Xsm = sm + 256 * WPAD;       // [64][128]
    const int t = blockIdx.x, tid = threadIdx.x;

    for (int i = tid; i < 256 * 128; i += 256) {
        int j = i >> 7, k = i & 127;
        Wsm[j * WPAD + k] = Wih[i];
    }
    const float* xt = x + (size_t)t * BB * DD;
    for (int i = tid; i < BB * DD; i += 256) Xsm[i] = xt[i];
    __syncthreads();

    const int bx = tid >> 5;
    const int jx = tid & 31;

    float bsum[8];
#pragma unroll
    for (int c = 0; c < 8; c++) {
        int j = jx + 32 * c;
        bsum[c] = bih[j] + bhh[j];
    }

    unsigned long long acc[8][8];
#pragma unroll
    for (int b = 0; b < 8; b++)
#pragma unroll
        for (int c = 0; c < 8; c++) acc[b][c] = 0ULL;

    const unsigned long long* Wu = (const unsigned long long*)Wsm;  // row stride 65
    const unsigned long long* Xu = (const unsigned long long*)Xsm;  // row stride 64

#pragma unroll 2
    for (int kp = 0; kp < 64; kp++) {
        unsigned long long w[8];
#pragma unroll
        for (int c = 0; c < 8; c++) w[c] = Wu[(jx + 32 * c) * 65 + kp];
#pragma unroll
        for (int b = 0; b < 8; b++) {
            unsigned long long a = Xu[(bx * 8 + b) * 64 + kp];
#pragma unroll
            for (int c = 0; c < 8; c++) FMA2(acc[b][c], w[c], a);
        }
    }

    float* op = g_xproj + (size_t)t * BB * HH;
#pragma unroll
    for (int b = 0; b < 8; b++) {
#pragma unroll
        for (int c = 0; c < 8; c++) {
            float2 f = up2(acc[b][c]);
            op[(bx * 8 + b) * HH + jx + 32 * c] = f.x + f.y + bsum[c];
        }
    }
}

// =====================================================================
// Kernel 2: recurrence + head.
// 64 clusters x 2 CTAs. row = tid>>3, sub = tid&7. Each thread: 16 local-half
// k + 16 remote-half k (warp-uniform phases, no divergence). Reduce = 3x
// shfl_xor within the 8-thread oct. One __syncthreads/step. h exchange via
// st.async + mbarrier complete_tx (R5 protocol, proven).
// hbuf layout [16][20] floats: 80B/group, bank-disjoint LDS.128.
// =====================================================================
__global__ void __launch_bounds__(1024, 1) __cluster_dims__(2, 1, 1)
rnn_kernel(const float* __restrict__ Whh, const float* __restrict__ Wfc,
           const float* __restrict__ bfc, float* __restrict__ out)
{
    __shared__ __align__(16) float hbuf[2][16][20];  // h[j] at [p][j>>4][j&15]
    __shared__ __align__(8) unsigned long long mbar_store;
    __shared__ float logits_sm[8];

    const int tid  = threadIdx.x;
    const int rank = blockIdx.x & 1;
    const int b    = blockIdx.x >> 1;
    const int row  = tid >> 3;    // 0..127 (local output row)
    const int sub  = tid & 7;     // k-subrange selector

    // --- W_hh slices into registers: row (rank*128+row), 16 local + 16 remote k ---
    unsigned long long W2[16];
    {
        const float* wrow = Whh + (size_t)(rank * 128 + row) * HH;
        const ulonglong2* pl =
            (const ulonglong2*)(wrow + rank * 128 + 16 * sub);
        const ulonglong2* pr =
            (const ulonglong2*)(wrow + (rank ^ 1) * 128 + 16 * sub);
#pragma unroll
        for (int m = 0; m < 4; m++) {
            ulonglong2 v = pl[m];
            W2[2 * m]     = v.x;
            W2[2 * m + 1] = v.y;
        }
#pragma unroll
        for (int m = 0; m < 4; m++) {
            ulonglong2 v = pr[m];
            W2[8 + 2 * m] = v.x;
            W2[9 + 2 * m] = v.y;
        }
    }

    // h0 = 0 (zero entire hbuf incl. pads)
    for (int i = tid; i < 2 * 16 * 20; i += 1024)
        ((float*)hbuf)[i] = 0.0f;

    const uint32_t mbar_local = smem_u32(&mbar_store);
    if (tid == 0) {
        asm volatile("mbarrier.init.shared.b64 [%0], %1;"
                     :: "r"(mbar_local), "r"(1) : "memory");
    }
    __syncthreads();
    asm volatile("barrier.cluster.arrive.aligned;" ::: "memory");
    asm volatile("barrier.cluster.wait.aligned;" ::: "memory");

    const uint32_t peer = rank ^ 1;
    uint32_t mbar_peer, hbuf_peer;
    asm("mapa.shared::cluster.u32 %0, %1, %2;" : "=r"(mbar_peer)
        : "r"(mbar_local), "r"(peer));
    asm("mapa.shared::cluster.u32 %0, %1, %2;" : "=r"(hbuf_peer)
        : "r"(smem_u32(&hbuf[0][0][0])), "r"(peer));

    // smem read bases (bytes) for this thread's k-groups
    const uint32_t hbase  = smem_u32(&hbuf[0][0][0]);
    const uint32_t off_loc = (uint32_t)((rank * 8 + sub) * 80);
    const uint32_t off_rem = (uint32_t)(((rank ^ 1) * 8 + sub) * 80);

    const bool writer = (sub == 0);
    // writer j = rank*128 + row; stored at [p][rank*8 + (row>>4)][row&15]
    const uint32_t wslot = (uint32_t)(((rank * 8 + (row >> 4)) * 20 + (row & 15)) * 4);

    const float* xrow = g_xproj + (size_t)b * HH + rank * 128 + row;
    const int xstride = BB * HH;

    int p = 0;
    float xp_cur = 0.0f, xp_next = 0.0f;
    if (writer) xp_cur = xrow[0];

#pragma unroll 1
    for (int t = 0; t < TT; t++) {
        if (writer && t + 1 < TT) xp_next = xrow[(size_t)(t + 1) * xstride];

        const uint32_t pb = hbase + (uint32_t)(p * 1280);

        // --- local-half partial (no wait needed; own CTA wrote it) ---
        const ulonglong2* hl = (const ulonglong2*)(uintptr_t)0;
        unsigned long long a0 = 0ULL, a1 = 0ULL;
        {
            const float* lp = (const float*)hbuf + ((pb + off_loc) - hbase) / 4;
            const ulonglong2* hu = (const ulonglong2*)lp;
#pragma unroll
            for (int m = 0; m < 4; m++) {
                ulonglong2 hv = hu[m];
                FMA2(a0, W2[2 * m],     hv.x);
                FMA2(a1, W2[2 * m + 1], hv.y);
            }
        }
        (void)hl;

        // --- wait for peer's half of h_t (pushed at end of its step t-1) ---
        if (t > 0) MBAR_WAIT(mbar_local, (t - 1) & 1);

        // --- remote-half partial ---
        {
            const float* rp = (const float*)hbuf + ((pb + off_rem) - hbase) / 4;
            const ulonglong2* hu = (const ulonglong2*)rp;
#pragma unroll
            for (int m = 0; m < 4; m++) {
                ulonglong2 hv = hu[m];
                FMA2(a0, W2[8 + 2 * m], hv.x);
                FMA2(a1, W2[9 + 2 * m], hv.y);
            }
        }

        float2 f0 = up2(a0), f1 = up2(a1);
        float s = (f0.x + f0.y) + (f1.x + f1.y);
        // reduce over 8 k-subranges (same warp oct)
        s += __shfl_xor_sync(0xffffffffu, s, 1);
        s += __shfl_xor_sync(0xffffffffu, s, 2);
        s += __shfl_xor_sync(0xffffffffu, s, 4);

        const int pn = p ^ 1;
        if (writer) {
            float hn = tanh_fast(s + xp_cur);
            // own copy
            *(float*)((char*)hbuf + (uint32_t)(pn * 1280) + wslot) = hn;
            // push to peer (transaction-counted, no remote arrive)
            if ((rank == 1) || (t + 1 < TT)) {
                uint32_t dst = hbuf_peer + (uint32_t)(pn * 1280) + wslot;
                asm volatile(
                    "st.async.shared::cluster.mbarrier::complete_tx::bytes.b32 [%0], %1, [%2];"
                    :: "r"(dst), "r"(__float_as_uint(hn)), "r"(mbar_peer) : "memory");
            }
        }
        // arm local mbar: 1 arrival + 512B tx completes phase t
        if (tid == 0 && ((rank == 0) || (t + 1 < TT))) {
            asm volatile("mbarrier.arrive.expect_tx.shared.b64 _, [%0], %1;"
                         :: "r"(mbar_local), "r"(512) : "memory");
        }
        __syncthreads();  // local-half writes visible CTA-wide

        p ^= 1;
        xp_cur = xp_next;
    }

    // --- head: rank 0 waits for rank1's final push, logits + log_softmax ---
    if (rank == 0) {
        MBAR_WAIT(mbar_local, 1);  // phase TT-1 (parity 1)
        // h_last in hbuf[0]; h[j] at hbuf[0][j>>4][j&15]
        const int w = tid >> 5, l = tid & 31;
        if (w < CC) {
            float sacc = 0.0f;
#pragma unroll
            for (int q = 0; q < 8; q++) {
                int j = l + 32 * q;
                sacc += hbuf[0][j >> 4][j & 15] * Wfc[w * HH + j];
            }
#pragma unroll
            for (int off = 16; off > 0; off >>= 1)
                sacc += __shfl_xor_sync(0xffffffffu, sacc, off);
            if (l == 0) logits_sm[w] = sacc + bfc[w];
        }
        __syncthreads();
        if (tid == 0) {
            float m = logits_sm[0];
#pragma unroll
            for (int c = 1; c < CC; c++) m = fmaxf(m, logits_sm[c]);
            float se = 0.0f;
#pragma unroll
            for (int c = 0; c < CC; c++) se += expf(logits_sm[c] - m);
            float lse = logf(se);
#pragma unroll
            for (int c = 0; c < CC; c++)
                out[b * CC + c] = logits_sm[c] - m - lse;
        }
    }
}

// =====================================================================
// launch
// =====================================================================
extern "C" void kernel_launch(void* const* d_in, const int* in_sizes, int n_in,
                              void* d_out, int out_size)
{
    const float* inputs = (const float*)d_in[0];
    const float* W_ih   = (const float*)d_in[1];
    const float* W_hh   = (const float*)d_in[2];
    const float* b_ih   = (const float*)d_in[3];
    const float* b_hh   = (const float*)d_in[4];
    const float* W_fc   = (const float*)d_in[5];
    const float* b_fc   = (const float*)d_in[6];
    float* out = (float*)d_out;

    const int smem1 = (256 * WPAD + BB * DD) * (int)sizeof(float);  // ~166 KB
    static int configured = 0;
    if (!configured) {
        cudaFuncSetAttribute(xproj_kernel,
                             cudaFuncAttributeMaxDynamicSharedMemorySize, smem1);
        configured = 1;
    }

    xproj_kernel<<<TT, 256, smem1>>>(inputs, W_ih, b_ih, b_hh);
    rnn_kernel<<<2 * BB, 1024>>>(W_hh, W_fc, b_fc, out);
}

// round 12
// speedup vs baseline: 1.3824x; 1.3824x over previous
#include <cuda_runtime.h>
#include <cstdint>

// Problem dims
#define TT 2048
#define BB 64
#define DD 128
#define HH 256
#define CC 5

// 134 MB scratch for x_proj (allowed: __device__ global, no runtime alloc)
__device__ float g_xproj[TT * BB * HH];

// ---------- helpers ----------
__device__ __forceinline__ float2 up2(unsigned long long v) {
    float2 r;
    asm("mov.b64 {%0,%1}, %2;" : "=f"(r.x), "=f"(r.y) : "l"(v));
    return r;
}
#define FMA2(d, a, b) asm("fma.rn.f32x2 %0, %1, %2, %0;" : "+l"(d) : "l"(a), "l"(b))

__device__ __forceinline__ uint32_t smem_u32(const void* p) {
    uint32_t a;
    asm("{ .reg .u64 t; cvta.to.shared.u64 t, %1; cvt.u32.u64 %0, t; }" : "=r"(a) : "l"(p));
    return a;
}

// fast tanh: 1 - 2/(e^{2x}+1), err ~5e-7, clamped (correctness-proven in R6 pass)
__device__ __forceinline__ float tanh_fast(float x) {
    float xc = fminf(fmaxf(x, -15.0f), 15.0f);
    float e  = __expf(2.0f * xc);
    return fmaf(-2.0f, __frcp_rn(e + 1.0f), 1.0f);
}

// R5's exact wait (with sleep hint)
#define MBAR_WAIT(addr, parity)                                              \
    asm volatile(                                                            \
        "{\n\t.reg .pred P;\n"                                               \
        "W%=:\n\t"                                                           \
        "mbarrier.try_wait.parity.acquire.cta.shared::cta.b64 P, [%0], %1, 0x989680;\n\t" \
        "@!P bra W%=;\n\t}"                                                  \
        :: "r"(addr), "r"(parity) : "memory")

// =====================================================================
// Kernel 1: x_proj[t,b,j] = sum_k inputs[t,b,k] * W_ih[j,k] + b_ih[j] + b_hh[j]
// TWO timesteps per CTA: W staged once, reused. grid = 1024, 256 threads.
// =====================================================================
#define WPAD 130

__global__ __launch_bounds__(256) void xproj_kernel(
    const float* __restrict__ x, const float* __restrict__ Wih,
    const float* __restrict__ bih, const float* __restrict__ bhh)
{
    extern __shared__ float sm[];
    float* Wsm = sm;                    // [256][WPAD]
    float* Xsm = sm + 256 * WPAD;       // [2][64][128]
    const int t0 = blockIdx.x * 2, tid = threadIdx.x;

    for (int i = tid; i < 256 * 128; i += 256) {
        int j = i >> 7, k = i & 127;
        Wsm[j * WPAD + k] = Wih[i];
    }
    const float* xt = x + (size_t)t0 * BB * DD;
    for (int i = tid; i < 2 * BB * DD; i += 256) Xsm[i] = xt[i];
    __syncthreads();

    const int bx = tid >> 5;
    const int jx = tid & 31;

    float bsum[8];
#pragma unroll
    for (int c = 0; c < 8; c++) {
        int j = jx + 32 * c;
        bsum[c] = bih[j] + bhh[j];
    }

    const unsigned long long* Wu = (const unsigned long long*)Wsm;  // row stride 65

    for (int tt = 0; tt < 2; tt++) {
        unsigned long long acc[8][8];
#pragma unroll
        for (int b = 0; b < 8; b++)
#pragma unroll
            for (int c = 0; c < 8; c++) acc[b][c] = 0ULL;

        const unsigned long long* Xu =
            (const unsigned long long*)(Xsm + tt * BB * DD);  // row stride 64

#pragma unroll 2
        for (int kp = 0; kp < 64; kp++) {
            unsigned long long w[8];
#pragma unroll
            for (int c = 0; c < 8; c++) w[c] = Wu[(jx + 32 * c) * 65 + kp];
#pragma unroll
            for (int b = 0; b < 8; b++) {
                unsigned long long a = Xu[(bx * 8 + b) * 64 + kp];
#pragma unroll
                for (int c = 0; c < 8; c++) FMA2(acc[b][c], w[c], a);
            }
        }

        float* op = g_xproj + (size_t)(t0 + tt) * BB * HH;
#pragma unroll
        for (int b = 0; b < 8; b++) {
#pragma unroll
            for (int c = 0; c < 8; c++) {
                float2 f = up2(acc[b][c]);
                op[(bx * 8 + b) * HH + jx + 32 * c] = f.x + f.y + bsum[c];
            }
        }
    }
}

// =====================================================================
// Kernel 2: recurrence + head — R5 protocol, synchronization byte-faithful:
// arm sits at BOTTOM of loop, after the __syncthreads that orders it after
// the remote warps' phase-(t-1) waits (prevents double-arrive on a pending
// phase — the R8/R10 crash). Local-only tweaks: reducers keep own partial
// in a register; cheaper tanh.
// 64 clusters x 2 CTAs. CTA rank r holds W_hh rows [128r,128r+128) in regs.
// =====================================================================
__global__ void __launch_bounds__(1024, 1) __cluster_dims__(2, 1, 1)
rnn_kernel(const float* __restrict__ Whh, const float* __restrict__ Wfc,
           const float* __restrict__ bfc, float* __restrict__ out)
{
    __shared__ __align__(16) float hbuf[2][HH];
    __shared__ float psum[1024];
    __shared__ __align__(8) unsigned long long mbar_store;
    __shared__ float logits_sm[8];

    const int tid  = threadIdx.x;
    const int rank = blockIdx.x & 1;
    const int b    = blockIdx.x >> 1;
    const int jl   = tid & 127;   // output row within this CTA's half
    const int g    = tid >> 7;    // k-group (32 k each), warp-uniform
    const bool remote_warp = ((g >> 2) != rank);  // k-half produced by peer

    // --- W_hh slice into registers: row (rank*128+jl), k in [32g, 32g+32) ---
    unsigned long long W2[16];
    {
        const ulonglong2* p =
            (const ulonglong2*)(Whh + (size_t)(rank * 128 + jl) * HH + g * 32);
#pragma unroll
        for (int m = 0; m < 8; m++) {
            ulonglong2 v = p[m];
            W2[2 * m]     = v.x;
            W2[2 * m + 1] = v.y;
        }
    }

    // h0 = 0
    for (int i = tid; i < HH; i += 1024) hbuf[0][i] = 0.0f;

    const uint32_t mbar_local = smem_u32(&mbar_store);
    if (tid == 0) {
        asm volatile("mbarrier.init.shared.b64 [%0], %1;"
                     :: "r"(mbar_local), "r"(1) : "memory");
    }
    __syncthreads();
    asm volatile("barrier.cluster.arrive.aligned;" ::: "memory");
    asm volatile("barrier.cluster.wait.aligned;" ::: "memory");

    const uint32_t peer = rank ^ 1;
    uint32_t mbar_peer, hbuf_peer;
    asm("mapa.shared::cluster.u32 %0, %1, %2;" : "=r"(mbar_peer)
        : "r"(mbar_local), "r"(peer));
    asm("mapa.shared::cluster.u32 %0, %1, %2;" : "=r"(hbuf_peer)
        : "r"(smem_u32(&hbuf[0][0])), "r"(peer));

    const float* xrow = g_xproj + (size_t)b * HH + rank * 128 + tid;  // tid<128
    const int xstride = BB * HH;

    int p = 0;
    float xp_cur = 0.0f, xp_next = 0.0f;
    if (tid < 128) xp_cur = xrow[0];

    for (int t = 0; t < TT; t++) {
        if (tid < 128 && t + 1 < TT) xp_next = xrow[(size_t)(t + 1) * xstride];

        // remote-half warps wait for peer's push of h_t's other half
        if (remote_warp && t > 0) MBAR_WAIT(mbar_local, (t - 1) & 1);

        // --- matvec partial over k in [32g, 32g+32), 4 accumulators ---
        const ulonglong2* hu = (const ulonglong2*)(&hbuf[p][g * 32]);
        unsigned long long a0 = 0ULL, a1 = 0ULL, a2 = 0ULL, a3 = 0ULL;
#pragma unroll
        for (int mm = 0; mm < 4; mm++) {
            ulonglong2 h0 = hu[2 * mm];
            ulonglong2 h1 = hu[2 * mm + 1];
            FMA2(a0, W2[4 * mm],     h0.x);
            FMA2(a1, W2[4 * mm + 1], h0.y);
            FMA2(a2, W2[4 * mm + 2], h1.x);
            FMA2(a3, W2[4 * mm + 3], h1.y);
        }
        float2 f0 = up2(a0), f1 = up2(a1), f2 = up2(a2), f3 = up2(a3);
        float part = ((f0.x + f0.y) + (f1.x + f1.y)) +
                     ((f2.x + f2.y) + (f3.x + f3.y));
        if (tid >= 128) psum[tid] = part;  // reducers keep own partial in reg
        __syncthreads();  // also orders the arm below AFTER the phase-(t-1) waits

        // --- reduce 8 partials, tanh, publish (local STS + st.async push) ---
        if (tid < 128) {
            float r0 = part            + psum[tid + 128];
            float r1 = psum[tid + 256] + psum[tid + 384];
            float r2 = psum[tid + 512] + psum[tid + 640];
            float r3 = psum[tid + 768] + psum[tid + 896];
            float hn = tanh_fast(((r0 + r1) + (r2 + r3)) + xp_cur);
            int pn = p ^ 1;
            hbuf[pn][rank * 128 + tid] = hn;  // own copy
            // push to peer with transaction-counted completion (no remote arrive)
            if ((rank == 1) || (t + 1 < TT)) {
                uint32_t dst = hbuf_peer + (uint32_t)((pn * HH + rank * 128 + tid) * 4);
                asm volatile(
                    "st.async.shared::cluster.mbarrier::complete_tx::bytes.b32 [%0], %1, [%2];"
                    :: "r"(dst), "r"(__float_as_uint(hn)), "r"(mbar_peer) : "memory");
            }
        }
        // arm local mbar for phase t (R5's exact position: phase t-1 provably
        // complete here, so this arrive targets phase t)
        if (tid == 0 && ((rank == 0) || (t + 1 < TT))) {
            asm volatile("mbarrier.arrive.expect_tx.shared.b64 _, [%0], %1;"
                         :: "r"(mbar_local), "r"(512) : "memory");
        }
        __syncthreads();  // own half visible CTA-wide before next step

        p ^= 1;
        xp_cur = xp_next;
    }

    // --- head: rank 0 waits for rank1's final push, logits + log_softmax ---
    if (rank == 0) {
        MBAR_WAIT(mbar_local, 1);  // phase TT-1 (parity 1): rank1's last half
        // hbuf[0] holds complete h_last
        const int w = tid >> 5, l = tid & 31;
        if (w < CC) {
            float sacc = 0.0f;
#pragma unroll
            for (int q = 0; q < 8; q++)
                sacc += hbuf[0][l + 32 * q] * Wfc[w * HH + l + 32 * q];
#pragma unroll
            for (int off = 16; off > 0; off >>= 1)
                sacc += __shfl_xor_sync(0xffffffffu, sacc, off);
            if (l == 0) logits_sm[w] = sacc + bfc[w];
        }
        __syncthreads();
        if (tid == 0) {
            float m = logits_sm[0];
#pragma unroll
            for (int c = 1; c < CC; c++) m = fmaxf(m, logits_sm[c]);
            float se = 0.0f;
#pragma unroll
            for (int c = 0; c < CC; c++) se += expf(logits_sm[c] - m);
            float lse = logf(se);
#pragma unroll
            for (int c = 0; c < CC; c++)
                out[b * CC + c] = logits_sm[c] - m - lse;
        }
    }
}

// =====================================================================
// launch
// =====================================================================
extern "C" void kernel_launch(void* const* d_in, const int* in_sizes, int n_in,
                              void* d_out, int out_size)
{
    const float* inputs = (const float*)d_in[0];
    const float* W_ih   = (const float*)d_in[1];
    const float* W_hh   = (const float*)d_in[2];
    const float* b_ih   = (const float*)d_in[3];
    const float* b_hh   = (const float*)d_in[4];
    const float* W_fc   = (const float*)d_in[5];
    const float* b_fc   = (const float*)d_in[6];
    float* out = (float*)d_out;

    const int smem1 = (256 * WPAD + 2 * BB * DD) * (int)sizeof(float);  // ~194 KB
    static int configured = 0;
    if (!configured) {
        cudaFuncSetAttribute(xproj_kernel,
                             cudaFuncAttributeMaxDynamicSharedMemorySize, smem1);
        configured = 1;
    }

    xproj_kernel<<<TT / 2, 256, smem1>>>(inputs, W_ih, b_ih, b_hh);
    rnn_kernel<<<2 * BB, 1024>>>(W_hh, W_fc, b_fc, out);
}